// round 7
// baseline (speedup 1.0000x reference)
#include <cuda_runtime.h>
#include <cuda_bf16.h>

#define B_      8
#define NVAL    1024
#define MVAL    1024
#define CIN     8
#define CREP    9
#define COUT    16

#define NSG     8                    // n-splits across blocks per (b, m-tile)
#define NBLKN   (NVAL / NSG)         // 128 n per block
#define MBLK    128                  // m per block (4 per lane)
#define MT      (MVAL / MBLK)        // 8 m-tiles
#define WARPS   8                    // warps per block
#define NTHREADS (32 * WARPS)        // 256
#define NCHUNK  (NBLKN / WARPS)      // 16 n per warp

typedef unsigned long long u64;

// Partial sums: [NSG][B][M][CREP] = 2.36MB (L2-resident)
__device__ float g_part[NSG * B_ * MVAL * CREP];
// One ticket per (b, m-tile) group; finishing block resets it -> replay-safe.
__device__ int   g_cnt[B_ * MT];

__device__ __forceinline__ u64 pack2(float lo, float hi) {
    u64 r; asm("mov.b64 %0, {%1, %2};" : "=l"(r) : "f"(lo), "f"(hi)); return r;
}
__device__ __forceinline__ void unpack2(u64 v, float& lo, float& hi) {
    asm("mov.b64 {%0, %1}, %2;" : "=f"(lo), "=f"(hi) : "l"(v));
}
__device__ __forceinline__ u64 add2(u64 a, u64 b) {
    u64 r; asm("add.rn.f32x2 %0, %1, %2;" : "=l"(r) : "l"(a), "l"(b)); return r;
}
__device__ __forceinline__ u64 mul2(u64 a, u64 b) {
    u64 r; asm("mul.rn.f32x2 %0, %1, %2;" : "=l"(r) : "l"(a), "l"(b)); return r;
}
__device__ __forceinline__ u64 fma2(u64 a, u64 b, u64 c) {
    u64 r; asm("fma.rn.f32x2 %0, %1, %2, %3;" : "=l"(r) : "l"(a), "l"(b), "l"(c)); return r;
}
__device__ __forceinline__ float ex2(float x) {   // MUFU.EX2
    float r; asm("ex2.approx.f32 %0, %1;" : "=f"(r) : "f"(x)); return r;
}

// One accumulation chain over two n-points. ALL locals underscore-prefixed:
// macro args are caller identifiers and MUST NOT be shadowed (R6 bug: a local
// `d0` captured the caller's `d0` accumulator).
#define CHAIN_STEP(tt, ntt, dAcc, A12, A34, A56, A78)                        \
    {                                                                        \
        u64 _dd = mul2(add2(x2, ntt), add2(xn2, tt));   /* -(x-t)^2 */       \
        float _f0, _f1; unpack2(_dd, _f0, _f1);                              \
        float _e0 = ex2(_f0), _e1 = ex2(_f1);                                \
        dAcc = add2(dAcc, pack2(_e0, _e1));                                  \
        u64 _e00 = pack2(_e0, _e0), _e11 = pack2(_e1, _e1);                  \
        A12 = fma2(_e00, yA.x, A12);  A34 = fma2(_e00, yA.y, A34);           \
        A56 = fma2(_e00, yB.x, A56);  A78 = fma2(_e00, yB.y, A78);           \
        A12 = fma2(_e11, zA.x, A12);  A34 = fma2(_e11, zA.y, A34);           \
        A56 = fma2(_e11, zB.x, A56);  A78 = fma2(_e11, zB.y, A78);           \
    }

__global__ __launch_bounds__(NTHREADS, 2)
void convcnp_fused(const float* __restrict__ gx,
                   const float* __restrict__ gy,
                   const float* __restrict__ gt,
                   const float* __restrict__ gsigma,
                   const float* __restrict__ gW,
                   const float* __restrict__ gbias,
                   float* __restrict__ gout)
{
    __shared__ float s_x [NBLKN];
    __shared__ float s_xn[NBLKN];
    __shared__ float s_pool[WARPS * MBLK * CREP];   // 9216 floats; first 1024 double as s_y
    __shared__ int   s_last;

    float* s_y = s_pool;

    const int nb   = blockIdx.x & (NSG - 1);
    const int mt   = (blockIdx.x >> 3) & (MT - 1);
    const int b    = blockIdx.x >> 6;
    const int tid  = threadIdx.x;
    const int lane = tid & 31;
    const int ns   = tid >> 5;

    float kk[CREP];
    bool same = true;
    #pragma unroll
    for (int c = 0; c < CREP; c++) {
        float s = __expf(gsigma[c]);
        kk[c] = -0.5f * 1.4426950408889634f / (s * s);
        if (c > 0 && kk[c] != kk[0]) same = false;
    }
    const float sf = same ? sqrtf(-kk[0]) : 1.0f;

    const int nbase = nb * NBLKN;

    for (int i = tid; i < NBLKN; i += NTHREADS) {
        float v = gx[b * NVAL + nbase + i] * sf;
        s_x [i] =  v;
        s_xn[i] = -v;
    }
    {
        const float4* y4 = (const float4*)(gy + (b * NVAL + nbase) * CIN);
        float4* sy4 = (float4*)s_y;
        sy4[tid] = y4[tid];                  // 256 x 16B = 4KB exactly (NBLKN*CIN)
    }
    const int   mg  = mt * MBLK + lane;
    const float tm0 = gt[b * MVAL + mg      ] * sf;
    const float tm1 = gt[b * MVAL + mg + 32 ] * sf;
    const float tm2 = gt[b * MVAL + mg + 64 ] * sf;
    const float tm3 = gt[b * MVAL + mg + 96 ] * sf;
    __syncthreads();

    const int n0 = ns * NCHUNK;
    float sum[4][CREP];

    if (same) {
        const u64 tt0 = pack2( tm0,  tm0), nt0 = pack2(-tm0, -tm0);
        const u64 tt1 = pack2( tm1,  tm1), nt1 = pack2(-tm1, -tm1);
        const u64 tt2 = pack2( tm2,  tm2), nt2 = pack2(-tm2, -tm2);
        const u64 tt3 = pack2( tm3,  tm3), nt3 = pack2(-tm3, -tm3);
        u64 d0 = 0, P12 = 0, P34 = 0, P56 = 0, P78 = 0;
        u64 d1 = 0, Q12 = 0, Q34 = 0, Q56 = 0, Q78 = 0;
        u64 d2 = 0, R12 = 0, R34 = 0, R56 = 0, R78 = 0;
        u64 d3 = 0, S12 = 0, S34 = 0, S56 = 0, S78 = 0;

        #pragma unroll 4
        for (int n = n0; n < n0 + NCHUNK; n += 2) {
            u64 x2  = *(const u64*)&s_x [n];
            u64 xn2 = *(const u64*)&s_xn[n];
            ulonglong2 yA = *(const ulonglong2*)&s_y[n * CIN];
            ulonglong2 yB = *(const ulonglong2*)&s_y[n * CIN + 4];
            ulonglong2 zA = *(const ulonglong2*)&s_y[(n + 1) * CIN];
            ulonglong2 zB = *(const ulonglong2*)&s_y[(n + 1) * CIN + 4];

            CHAIN_STEP(tt0, nt0, d0, P12, P34, P56, P78)
            CHAIN_STEP(tt1, nt1, d1, Q12, Q34, Q56, Q78)
            CHAIN_STEP(tt2, nt2, d2, R12, R34, R56, R78)
            CHAIN_STEP(tt3, nt3, d3, S12, S34, S56, S78)
        }
        float lo, hi;
        unpack2(d0, lo, hi);  sum[0][0] = lo + hi;
        unpack2(P12, sum[0][1], sum[0][2]); unpack2(P34, sum[0][3], sum[0][4]);
        unpack2(P56, sum[0][5], sum[0][6]); unpack2(P78, sum[0][7], sum[0][8]);
        unpack2(d1, lo, hi);  sum[1][0] = lo + hi;
        unpack2(Q12, sum[1][1], sum[1][2]); unpack2(Q34, sum[1][3], sum[1][4]);
        unpack2(Q56, sum[1][5], sum[1][6]); unpack2(Q78, sum[1][7], sum[1][8]);
        unpack2(d2, lo, hi);  sum[2][0] = lo + hi;
        unpack2(R12, sum[2][1], sum[2][2]); unpack2(R34, sum[2][3], sum[2][4]);
        unpack2(R56, sum[2][5], sum[2][6]); unpack2(R78, sum[2][7], sum[2][8]);
        unpack2(d3, lo, hi);  sum[3][0] = lo + hi;
        unpack2(S12, sum[3][1], sum[3][2]); unpack2(S34, sum[3][3], sum[3][4]);
        unpack2(S56, sum[3][5], sum[3][6]); unpack2(S78, sum[3][7], sum[3][8]);
    } else {
        float tmv[4] = {tm0, tm1, tm2, tm3};
        #pragma unroll
        for (int q = 0; q < 4; q++)
            #pragma unroll
            for (int c = 0; c < CREP; c++) sum[q][c] = 0.0f;
        for (int n = n0; n < n0 + NCHUNK; n++) {
            float xv = s_x[n];
            const float4 ya = *(const float4*)&s_y[n * CIN];
            const float4 yb = *(const float4*)&s_y[n * CIN + 4];
            #pragma unroll
            for (int q = 0; q < 4; q++) {
                float a = xv - tmv[q], d = a * a;
                sum[q][0] += ex2(d * kk[0]);
                sum[q][1] = fmaf(ex2(d * kk[1]), ya.x, sum[q][1]);
                sum[q][2] = fmaf(ex2(d * kk[2]), ya.y, sum[q][2]);
                sum[q][3] = fmaf(ex2(d * kk[3]), ya.z, sum[q][3]);
                sum[q][4] = fmaf(ex2(d * kk[4]), ya.w, sum[q][4]);
                sum[q][5] = fmaf(ex2(d * kk[5]), yb.x, sum[q][5]);
                sum[q][6] = fmaf(ex2(d * kk[6]), yb.y, sum[q][6]);
                sum[q][7] = fmaf(ex2(d * kk[7]), yb.z, sum[q][7]);
                sum[q][8] = fmaf(ex2(d * kk[8]), yb.w, sum[q][8]);
            }
        }
    }

    // Block-local reduce over the 8 warps -> one partial slice to global scratch.
    __syncthreads();                       // s_y no longer needed
    float* red = s_pool;                   // [WARPS][MBLK][CREP]
    #pragma unroll
    for (int q = 0; q < 4; q++)
        #pragma unroll
        for (int c = 0; c < CREP; c++)
            red[(ns * MBLK + lane + q * 32) * CREP + c] = sum[q][c];
    __syncthreads();

    const int base = ((nb * B_ + b) * MVAL + mt * MBLK) * CREP;
    for (int i = tid; i < MBLK * CREP; i += NTHREADS) {
        float s = 0.0f;
        #pragma unroll
        for (int w = 0; w < WARPS; w++)
            s += red[w * (MBLK * CREP) + i];
        g_part[base + i] = s;
    }

    // Release: every thread fences its own g_part stores, then block sync,
    // then one atomic per block.
    __threadfence();
    __syncthreads();
    if (tid == 0) {
        int old = atomicAdd(&g_cnt[b * MT + mt], 1);
        s_last = (old == NSG - 1);
        if (s_last) g_cnt[b * MT + mt] = 0;   // replay-safe reset
    }
    __syncthreads();
    if (!s_last) return;
    __threadfence();   // acquire before reading other blocks' slices

    // Finish: sum NSG slices (fixed order -> deterministic), normalize, GEMV.
    if (tid < MBLK) {
        const int m = mt * MBLK + tid;
        float tot[CREP];
        #pragma unroll
        for (int c = 0; c < CREP; c++) tot[c] = 0.0f;
        #pragma unroll
        for (int s = 0; s < NSG; s++) {
            const float* p = &g_part[((s * B_ + b) * MVAL + m) * CREP];
            #pragma unroll
            for (int c = 0; c < CREP; c++) tot[c] += p[c];
        }

        float density = tot[0];
        float inv = 1.0f / (density + 1e-8f);
        float yv[CREP];
        yv[0] = density;
        #pragma unroll
        for (int c = 1; c < CREP; c++) yv[c] = tot[c] * inv;

        float4 o4[COUT / 4];
        #pragma unroll
        for (int o = 0; o < COUT; o++) {
            float r = __ldg(&gbias[o]);
            #pragma unroll
            for (int c = 0; c < CREP; c++)
                r = fmaf(__ldg(&gW[o * CREP + c]), yv[c], r);
            ((float*)o4)[o] = r;
        }
        float4* orow = (float4*)(gout + ((size_t)b * MVAL + m) * COUT);
        #pragma unroll
        for (int q = 0; q < COUT / 4; q++) orow[q] = o4[q];
    }
}

extern "C" void kernel_launch(void* const* d_in, const int* in_sizes, int n_in,
                              void* d_out, int out_size) {
    const float* x     = (const float*)d_in[0];
    const float* y     = (const float*)d_in[1];
    const float* t     = (const float*)d_in[2];
    const float* sigma = (const float*)d_in[3];
    const float* W     = (const float*)d_in[4];
    const float* bias  = (const float*)d_in[5];
    float* out = (float*)d_out;

    convcnp_fused<<<B_ * MT * NSG, NTHREADS>>>(x, y, t, sigma, W, bias, out); // 512 blocks
}

// round 8
// speedup vs baseline: 1.2608x; 1.2608x over previous
#include <cuda_runtime.h>
#include <cuda_bf16.h>

#define B_      8
#define NVAL    1024
#define MVAL    1024
#define CIN     8
#define CREP    9
#define COUT    16

#define MBLK    16                   // m per block (per warp: lanes 0-15)
#define MT      (MVAL / MBLK)        // 64 m-tiles -> grid = 8*64 = 512
#define WARPS   8
#define NTHREADS (32 * WARPS)        // 256
#define NWCHUNK (NVAL / WARPS)       // 128 n per warp

typedef unsigned long long u64;

__device__ __forceinline__ u64 pack2(float lo, float hi) {
    u64 r; asm("mov.b64 %0, {%1, %2};" : "=l"(r) : "f"(lo), "f"(hi)); return r;
}
__device__ __forceinline__ void unpack2(u64 v, float& lo, float& hi) {
    asm("mov.b64 {%0, %1}, %2;" : "=f"(lo), "=f"(hi) : "l"(v));
}
__device__ __forceinline__ u64 add2(u64 a, u64 b) {
    u64 r; asm("add.rn.f32x2 %0, %1, %2;" : "=l"(r) : "l"(a), "l"(b)); return r;
}
__device__ __forceinline__ u64 mul2(u64 a, u64 b) {
    u64 r; asm("mul.rn.f32x2 %0, %1, %2;" : "=l"(r) : "l"(a), "l"(b)); return r;
}
__device__ __forceinline__ u64 fma2(u64 a, u64 b, u64 c) {
    u64 r; asm("fma.rn.f32x2 %0, %1, %2, %3;" : "=l"(r) : "l"(a), "l"(b), "l"(c)); return r;
}
__device__ __forceinline__ float ex2(float x) {   // MUFU.EX2
    float r; asm("ex2.approx.f32 %0, %1;" : "=f"(r) : "f"(x)); return r;
}

__global__ __launch_bounds__(NTHREADS)
void convcnp_one(const float* __restrict__ gx,
                 const float* __restrict__ gy,
                 const float* __restrict__ gt,
                 const float* __restrict__ gsigma,
                 const float* __restrict__ gW,
                 const float* __restrict__ gbias,
                 float* __restrict__ gout)
{
    __shared__ float s_x [NVAL];         // sf*x        (4KB)  -> s_tot after loop
    __shared__ float s_xn[NVAL];         // -sf*x       (4KB)
    __shared__ float s_y [NVAL * CIN];   // y           (32KB) -> red after loop

    const int b    = blockIdx.x >> 6;    // MT = 64
    const int mt   = blockIdx.x & (MT - 1);
    const int tid  = threadIdx.x;
    const int lane = tid & 31;
    const int w    = tid >> 5;
    const int ml   = lane & (MBLK - 1);  // local m
    const int nsub = lane >> 4;          // 0/1: even/odd n-pair

    float kk[CREP];
    bool same = true;
    #pragma unroll
    for (int c = 0; c < CREP; c++) {
        float s = __expf(gsigma[c]);
        kk[c] = -0.5f * 1.4426950408889634f / (s * s);
        if (c > 0 && kk[c] != kk[0]) same = false;
    }
    const float sf = same ? sqrtf(-kk[0]) : 1.0f;

    for (int i = tid; i < NVAL; i += NTHREADS) {
        float v = gx[b * NVAL + i] * sf;
        s_x [i] =  v;
        s_xn[i] = -v;
    }
    {
        const float4* y4 = (const float4*)(gy + b * NVAL * CIN);
        float4* sy4 = (float4*)s_y;
        #pragma unroll
        for (int i = tid; i < NVAL * CIN / 4; i += NTHREADS)
            sy4[i] = y4[i];
    }
    const int   m   = mt * MBLK + ml;
    const float tm  = gt[b * MVAL + m] * sf;
    __syncthreads();

    const int n0 = w * NWCHUNK + 2 * nsub;
    float sum[CREP];

    if (same) {
        const u64 tt  = pack2( tm,  tm), ntt = pack2(-tm, -tm);
        u64 dd0 = 0, A12 = 0, A34 = 0, A56 = 0, A78 = 0;

        #pragma unroll 4
        for (int i = 0; i < NWCHUNK / 4; i++) {
            const int n = n0 + 4 * i;
            u64 x2  = *(const u64*)&s_x [n];
            u64 xn2 = *(const u64*)&s_xn[n];
            ulonglong2 yA = *(const ulonglong2*)&s_y[n * CIN];
            ulonglong2 yB = *(const ulonglong2*)&s_y[n * CIN + 4];
            ulonglong2 zA = *(const ulonglong2*)&s_y[(n + 1) * CIN];
            ulonglong2 zB = *(const ulonglong2*)&s_y[(n + 1) * CIN + 4];

            u64 dsq = mul2(add2(x2, ntt), add2(xn2, tt));   // -(x-t)^2 (pre-scaled)
            float f0, f1; unpack2(dsq, f0, f1);
            float e0 = ex2(f0), e1 = ex2(f1);
            dd0 = add2(dd0, pack2(e0, e1));
            u64 e00 = pack2(e0, e0), e11 = pack2(e1, e1);
            A12 = fma2(e00, yA.x, A12);  A34 = fma2(e00, yA.y, A34);
            A56 = fma2(e00, yB.x, A56);  A78 = fma2(e00, yB.y, A78);
            A12 = fma2(e11, zA.x, A12);  A34 = fma2(e11, zA.y, A34);
            A56 = fma2(e11, zB.x, A56);  A78 = fma2(e11, zB.y, A78);
        }
        // Merge the two n-halves (lane ^ 16 holds the same m).
        dd0 = add2(dd0, __shfl_xor_sync(0xffffffffu, dd0, 16));
        A12 = add2(A12, __shfl_xor_sync(0xffffffffu, A12, 16));
        A34 = add2(A34, __shfl_xor_sync(0xffffffffu, A34, 16));
        A56 = add2(A56, __shfl_xor_sync(0xffffffffu, A56, 16));
        A78 = add2(A78, __shfl_xor_sync(0xffffffffu, A78, 16));

        float lo, hi;
        unpack2(dd0, lo, hi);  sum[0] = lo + hi;
        unpack2(A12, sum[1], sum[2]); unpack2(A34, sum[3], sum[4]);
        unpack2(A56, sum[5], sum[6]); unpack2(A78, sum[7], sum[8]);
    } else {
        #pragma unroll
        for (int c = 0; c < CREP; c++) sum[c] = 0.0f;
        for (int i = 0; i < NWCHUNK / 4; i++) {
            const int nb2 = n0 + 4 * i;
            #pragma unroll
            for (int k = 0; k < 2; k++) {
                const int n = nb2 + k;
                float a = s_x[n] - tm, d = a * a;
                const float4 ya = *(const float4*)&s_y[n * CIN];
                const float4 yb = *(const float4*)&s_y[n * CIN + 4];
                sum[0] += ex2(d * kk[0]);
                sum[1] = fmaf(ex2(d * kk[1]), ya.x, sum[1]);
                sum[2] = fmaf(ex2(d * kk[2]), ya.y, sum[2]);
                sum[3] = fmaf(ex2(d * kk[3]), ya.z, sum[3]);
                sum[4] = fmaf(ex2(d * kk[4]), ya.w, sum[4]);
                sum[5] = fmaf(ex2(d * kk[5]), yb.x, sum[5]);
                sum[6] = fmaf(ex2(d * kk[6]), yb.y, sum[6]);
                sum[7] = fmaf(ex2(d * kk[7]), yb.z, sum[7]);
                sum[8] = fmaf(ex2(d * kk[8]), yb.w, sum[8]);
            }
        }
        #pragma unroll
        for (int c = 0; c < CREP; c++)
            sum[c] += __shfl_xor_sync(0xffffffffu, sum[c], 16);
    }

    // Cross-warp reduce: red[w][ml][c] in (retired) s_y space.
    __syncthreads();
    float* red = s_y;                      // [WARPS][MBLK][CREP] = 1152 floats
    if (nsub == 0) {
        #pragma unroll
        for (int c = 0; c < CREP; c++)
            red[(w * MBLK + ml) * CREP + c] = sum[c];
    }
    __syncthreads();

    float* s_tot = s_x;                    // [MBLK][CREP] = 144 floats (s_x retired)
    if (tid < MBLK * CREP) {
        float s = 0.0f;
        #pragma unroll
        for (int ww = 0; ww < WARPS; ww++)
            s += red[ww * (MBLK * CREP) + tid];
        s_tot[tid] = s;
    }
    __syncthreads();

    // GEMV: thread t -> (m = t>>4, o = t&15). 256 threads = 16m x 16o.
    {
        const int mm = tid >> 4;
        const int o  = tid & (COUT - 1);
        const float density = s_tot[mm * CREP];
        const float inv = 1.0f / (density + 1e-8f);
        float r = __ldg(&gbias[o]) + __ldg(&gW[o * CREP]) * density;
        #pragma unroll
        for (int c = 1; c < CREP; c++)
            r = fmaf(__ldg(&gW[o * CREP + c]), s_tot[mm * CREP + c] * inv, r);
        gout[((size_t)b * MVAL + mt * MBLK + mm) * COUT + o] = r;
    }
}

extern "C" void kernel_launch(void* const* d_in, const int* in_sizes, int n_in,
                              void* d_out, int out_size) {
    const float* x     = (const float*)d_in[0];
    const float* y     = (const float*)d_in[1];
    const float* t     = (const float*)d_in[2];
    const float* sigma = (const float*)d_in[3];
    const float* W     = (const float*)d_in[4];
    const float* bias  = (const float*)d_in[5];
    float* out = (float*)d_out;

    convcnp_one<<<B_ * MT, NTHREADS>>>(x, y, t, sigma, W, bias, out);  // 512 blocks
}